// round 4
// baseline (speedup 1.0000x reference)
#include <cuda_runtime.h>

// EdgeUpdateNetwork: T=8, N=256, F=128
//
// Factorization: y[t,i,j,f] = A[t,i,f] + B[t,j,f] where
//   A = x @ w[:, :F]^T,  B = x @ w[:, F:]^T
// BN stats in closed form from A/B reductions; then fused
// affine+relu+diag-zero+L1-normalize streaming kernel writes 537MB.

#define T_DIM 8
#define N_DIM 256
#define F_DIM 128
#define M_DIM (T_DIM * N_DIM)   // 2048 rows
#define O_DIM 512               // A1 | B1 | A2 | B2

// Scratch (device globals — no allocation allowed)
__device__ float g_Y[M_DIM * O_DIM];   // 4 MB: Y[m][o]
__device__ float g_sh[4 * F_DIM];      // [br*256 + f] = scale, [br*256+128+f] = shift

// ---------------------------------------------------------------------------
// Kernel 1: X[2048,128] @ W^T[128,512] -> Y[2048,512]
// o mapping: o<128: w1[o, c] ; 128<=o<256: w1[o-128, 128+c]
//            256<=o<384: w2[o-256, c] ; 384<=o: w2[o-384, 128+c]
// 64x64 tile per block, 256 threads, 4x4 micro-tile, K chunks of 16.
// ---------------------------------------------------------------------------
__global__ void gemm_kernel(const float* __restrict__ X,
                            const float* __restrict__ w1,
                            const float* __restrict__ w2) {
    __shared__ float Xs[16][65];
    __shared__ float Ws[16][65];
    const int m0 = blockIdx.y * 64;
    const int o0 = blockIdx.x * 64;
    const int tid = threadIdx.x;
    const int tx = tid & 15, ty = tid >> 4;
    const float* wbase = (o0 < 256) ? w1 : w2;  // o0 multiple of 64, never straddles

    float acc[4][4] = {};

    for (int kc = 0; kc < 128; kc += 16) {
        #pragma unroll
        for (int r = 0; r < 4; r++) {
            int e = tid + r * 256;     // 0..1023
            int kk = e & 15, d = e >> 4;  // d: 0..63
            Xs[kk][d] = X[(m0 + d) * 128 + kc + kk];
            int o = o0 + d;
            int f = o & 127, half = (o >> 7) & 1;
            Ws[kk][d] = wbase[f * 256 + half * 128 + kc + kk];
        }
        __syncthreads();
        #pragma unroll
        for (int kk = 0; kk < 16; kk++) {
            float xr[4], wr[4];
            #pragma unroll
            for (int a = 0; a < 4; a++) xr[a] = Xs[kk][ty * 4 + a];
            #pragma unroll
            for (int b = 0; b < 4; b++) wr[b] = Ws[kk][tx * 4 + b];
            #pragma unroll
            for (int a = 0; a < 4; a++)
                #pragma unroll
                for (int b = 0; b < 4; b++)
                    acc[a][b] = fmaf(xr[a], wr[b], acc[a][b]);
        }
        __syncthreads();
    }
    #pragma unroll
    for (int a = 0; a < 4; a++)
        #pragma unroll
        for (int b = 0; b < 4; b++)
            g_Y[(m0 + ty * 4 + a) * O_DIM + o0 + tx * 4 + b] = acc[a][b];
}

// ---------------------------------------------------------------------------
// Kernel 2: closed-form BN stats per (branch, f).
//   mean = (sumA + sumB) / (T*N)
//   E[y^2] = (N*(sumA2 + sumB2) + 2*sum_t SA_t*SB_t) / (T*N*N)
//   fold: s = g * rsqrt(var+eps), h = b - mean*s
// 256 blocks (br*128+f), 256 threads; warp w == t (32 thr * 8 m = 256 = N).
// ---------------------------------------------------------------------------
__global__ void stats_kernel(const float* __restrict__ gamma1,
                             const float* __restrict__ beta1,
                             const float* __restrict__ gamma2,
                             const float* __restrict__ beta2) {
    const int bf = blockIdx.x;
    const int br = bf >> 7, f = bf & 127;
    const int colA = br * 256 + f;
    const int colB = colA + 128;
    const int tid = threadIdx.x;

    float sa = 0.f, sa2 = 0.f, sb = 0.f, sb2 = 0.f;
    #pragma unroll
    for (int k = 0; k < 8; k++) {
        int m = tid * 8 + k;
        float a = g_Y[m * O_DIM + colA];
        float b = g_Y[m * O_DIM + colB];
        sa += a;  sa2 = fmaf(a, a, sa2);
        sb += b;  sb2 = fmaf(b, b, sb2);
    }
    #pragma unroll
    for (int off = 16; off; off >>= 1) {
        sa  += __shfl_xor_sync(0xffffffffu, sa,  off);
        sa2 += __shfl_xor_sync(0xffffffffu, sa2, off);
        sb  += __shfl_xor_sync(0xffffffffu, sb,  off);
        sb2 += __shfl_xor_sync(0xffffffffu, sb2, off);
    }
    __shared__ float SA[8], SB[8], SA2[8], SB2[8];
    int w = tid >> 5;
    if ((tid & 31) == 0) { SA[w] = sa; SB[w] = sb; SA2[w] = sa2; SB2[w] = sb2; }
    __syncthreads();
    if (tid == 0) {
        float sumA = 0.f, sumB = 0.f, sumA2 = 0.f, sumB2 = 0.f, cross = 0.f;
        #pragma unroll
        for (int t = 0; t < 8; t++) {
            sumA  += SA[t];  sumB  += SB[t];
            sumA2 += SA2[t]; sumB2 += SB2[t];
            cross = fmaf(SA[t], SB[t], cross);
        }
        float mean = (sumA + sumB) * (1.0f / 2048.0f);
        float ey2  = (256.0f * (sumA2 + sumB2) + 2.0f * cross) * (1.0f / 524288.0f);
        float var  = ey2 - mean * mean;
        float g  = br ? gamma2[f] : gamma1[f];
        float bb = br ? beta2[f]  : beta1[f];
        float s  = g * rsqrtf(var + 1e-5f);
        g_sh[br * 256 + f]       = s;
        g_sh[br * 256 + 128 + f] = bb - mean * s;
    }
}

// ---------------------------------------------------------------------------
// Kernel 3: streaming epilogue.
// Block = (t, branch, 8-row i-tile); 8 warps, warp w handles j in [w*32, w*32+32).
// Per j-row: v = relu(fma(b, s, fma(a, s, h))), diag -> 0, warp L1 sum,
// fast reciprocal, STG.128. 537 MB of writes -> HBM-bound.
// ---------------------------------------------------------------------------
__global__ void __launch_bounds__(256) edge_kernel(float* __restrict__ out) {
    const int bid = blockIdx.x;          // 512 blocks
    const int itile = bid & 31;
    const int br = (bid >> 5) & 1;
    const int t = bid >> 6;
    const int i0 = itile * 8;
    const int tid = threadIdx.x;
    const int w = tid >> 5, l = tid & 31;
    const int f0 = l * 4;

    const float4 s4 = *(const float4*)&g_sh[br * 256 + f0];
    const float4 h4 = *(const float4*)&g_sh[br * 256 + 128 + f0];
    const int baseA = br * 256 + f0;
    const int baseB = baseA + 128;

    for (int ii = 0; ii < 8; ii++) {
        const int i = i0 + ii;
        const int mi = t * 256 + i;
        const float4 a4 = *(const float4*)&g_Y[mi * O_DIM + baseA];
        const float px = fmaf(a4.x, s4.x, h4.x);
        const float py = fmaf(a4.y, s4.y, h4.y);
        const float pz = fmaf(a4.z, s4.z, h4.z);
        const float pw = fmaf(a4.w, s4.w, h4.w);
        const size_t rowbase = (size_t)((t * 2 + br) * 256 + i) * (256 * 128);

        #pragma unroll 4
        for (int jj = 0; jj < 32; jj++) {
            const int j = w * 32 + jj;
            const int mj = t * 256 + j;
            const float4 b4 = *(const float4*)&g_Y[mj * O_DIM + baseB];
            float vx = fmaxf(fmaf(b4.x, s4.x, px), 0.0f);
            float vy = fmaxf(fmaf(b4.y, s4.y, py), 0.0f);
            float vz = fmaxf(fmaf(b4.z, s4.z, pz), 0.0f);
            float vw = fmaxf(fmaf(b4.w, s4.w, pw), 0.0f);
            if (j == i) { vx = 0.f; vy = 0.f; vz = 0.f; vw = 0.f; }
            float sm = (vx + vy) + (vz + vw);
            #pragma unroll
            for (int off = 16; off; off >>= 1)
                sm += __shfl_xor_sync(0xffffffffu, sm, off);
            const float inv = __fdividef(1.0f, fmaxf(sm, 1e-12f));
            float4 o4 = make_float4(vx * inv, vy * inv, vz * inv, vw * inv);
            *(float4*)&out[rowbase + (size_t)j * 128 + f0] = o4;
        }
    }
}

// ---------------------------------------------------------------------------
extern "C" void kernel_launch(void* const* d_in, const int* in_sizes, int n_in,
                              void* d_out, int out_size) {
    const float* x  = (const float*)d_in[0];   // node_feats [8,256,128]
    const float* w1 = (const float*)d_in[1];   // [128,256]
    const float* g1 = (const float*)d_in[2];
    const float* b1 = (const float*)d_in[3];
    const float* w2 = (const float*)d_in[4];
    const float* g2 = (const float*)d_in[5];
    const float* b2 = (const float*)d_in[6];
    float* out = (float*)d_out;                // [8,2,256,256,128] fp32

    dim3 ggrid(O_DIM / 64, M_DIM / 64);        // (8, 32)
    gemm_kernel<<<ggrid, 256>>>(x, w1, w2);
    stats_kernel<<<256, 256>>>(g1, b1, g2, b2);
    edge_kernel<<<512, 256>>>(out);
}

// round 5
// speedup vs baseline: 1.3391x; 1.3391x over previous
#include <cuda_runtime.h>

// EdgeUpdateNetwork: T=8, N=256, F=128
//
// Factorization: y[t,i,j,f] = A[t,i,f] + B[t,j,f] where
//   A = x @ w[:, :F]^T,  B = x @ w[:, F:]^T
// BN stats in closed form from A/B reductions; then fused
// affine+relu+diag-zero+L1-normalize streaming kernel writes 537MB.

#define T_DIM 8
#define N_DIM 256
#define F_DIM 128
#define M_DIM (T_DIM * N_DIM)   // 2048 rows
#define O_DIM 512               // A1 | B1 | A2 | B2

// Scratch (device globals — no allocation allowed)
__device__ float g_Y[M_DIM * O_DIM];   // 4 MB: Y[m][o]
__device__ float g_sh[4 * F_DIM];      // [br*256 + f] = scale, [br*256+128+f] = shift

// ---------------------------------------------------------------------------
// Kernel 1: X[2048,128] @ W^T[128,512] -> Y[2048,512]
// 32x64 tile per block (grid 8x64 = 512 blocks for occupancy), 256 threads,
// 2x4 micro-tile, K chunks of 16. Smem pads multiple-of-4 so LDS vectorizes.
// ---------------------------------------------------------------------------
__global__ void gemm_kernel(const float* __restrict__ X,
                            const float* __restrict__ w1,
                            const float* __restrict__ w2) {
    __shared__ float Xs[16][36];
    __shared__ float Ws[16][68];
    const int m0 = blockIdx.y * 32;
    const int o0 = blockIdx.x * 64;
    const int tid = threadIdx.x;
    const int tx = tid & 15, ty = tid >> 4;
    const float* wbase = (o0 < 256) ? w1 : w2;  // o0 multiple of 64, never straddles

    float acc[2][4] = {};

    for (int kc = 0; kc < 128; kc += 16) {
        // X tile: 16k x 32m = 512 elems, 2 per thread
        #pragma unroll
        for (int r = 0; r < 2; r++) {
            int e = tid + r * 256;
            int kk = e & 15, d = e >> 4;           // d: 0..31
            Xs[kk][d] = X[(m0 + d) * 128 + kc + kk];
        }
        // W tile: 16k x 64o = 1024 elems, 4 per thread
        #pragma unroll
        for (int r = 0; r < 4; r++) {
            int e = tid + r * 256;
            int kk = e & 15, d = e >> 4;           // d: 0..63
            int o = o0 + d;
            int f = o & 127, half = (o >> 7) & 1;
            Ws[kk][d] = wbase[f * 256 + half * 128 + kc + kk];
        }
        __syncthreads();
        #pragma unroll
        for (int kk = 0; kk < 16; kk++) {
            float xr[2], wr[4];
            #pragma unroll
            for (int a = 0; a < 2; a++) xr[a] = Xs[kk][ty * 2 + a];
            #pragma unroll
            for (int b = 0; b < 4; b++) wr[b] = Ws[kk][tx * 4 + b];
            #pragma unroll
            for (int a = 0; a < 2; a++)
                #pragma unroll
                for (int b = 0; b < 4; b++)
                    acc[a][b] = fmaf(xr[a], wr[b], acc[a][b]);
        }
        __syncthreads();
    }
    #pragma unroll
    for (int a = 0; a < 2; a++) {
        float4 v = make_float4(acc[a][0], acc[a][1], acc[a][2], acc[a][3]);
        *(float4*)&g_Y[(m0 + ty * 2 + a) * O_DIM + o0 + tx * 4] = v;
    }
}

// ---------------------------------------------------------------------------
// Kernel 2: closed-form BN stats per (branch, f).
//   mean = (sumA + sumB) / (T*N)
//   E[y^2] = (N*(sumA2 + sumB2) + 2*sum_t SA_t*SB_t) / (T*N*N)
//   fold: s = g * rsqrt(var+eps), h = b - mean*s
// ---------------------------------------------------------------------------
__global__ void stats_kernel(const float* __restrict__ gamma1,
                             const float* __restrict__ beta1,
                             const float* __restrict__ gamma2,
                             const float* __restrict__ beta2) {
    const int bf = blockIdx.x;
    const int br = bf >> 7, f = bf & 127;
    const int colA = br * 256 + f;
    const int colB = colA + 128;
    const int tid = threadIdx.x;

    float sa = 0.f, sa2 = 0.f, sb = 0.f, sb2 = 0.f;
    #pragma unroll
    for (int k = 0; k < 8; k++) {
        int m = tid * 8 + k;
        float a = g_Y[m * O_DIM + colA];
        float b = g_Y[m * O_DIM + colB];
        sa += a;  sa2 = fmaf(a, a, sa2);
        sb += b;  sb2 = fmaf(b, b, sb2);
    }
    #pragma unroll
    for (int off = 16; off; off >>= 1) {
        sa  += __shfl_xor_sync(0xffffffffu, sa,  off);
        sa2 += __shfl_xor_sync(0xffffffffu, sa2, off);
        sb  += __shfl_xor_sync(0xffffffffu, sb,  off);
        sb2 += __shfl_xor_sync(0xffffffffu, sb2, off);
    }
    __shared__ float SA[8], SB[8], SA2[8], SB2[8];
    int w = tid >> 5;
    if ((tid & 31) == 0) { SA[w] = sa; SB[w] = sb; SA2[w] = sa2; SB2[w] = sb2; }
    __syncthreads();
    if (tid == 0) {
        float sumA = 0.f, sumB = 0.f, sumA2 = 0.f, sumB2 = 0.f, cross = 0.f;
        #pragma unroll
        for (int t = 0; t < 8; t++) {
            sumA  += SA[t];  sumB  += SB[t];
            sumA2 += SA2[t]; sumB2 += SB2[t];
            cross = fmaf(SA[t], SB[t], cross);
        }
        float mean = (sumA + sumB) * (1.0f / 2048.0f);
        float ey2  = (256.0f * (sumA2 + sumB2) + 2.0f * cross) * (1.0f / 524288.0f);
        float var  = ey2 - mean * mean;
        float g  = br ? gamma2[f] : gamma1[f];
        float bb = br ? beta2[f]  : beta1[f];
        float s  = g * rsqrtf(var + 1e-5f);
        g_sh[br * 256 + f]       = s;
        g_sh[br * 256 + 128 + f] = bb - mean * s;
    }
}

// ---------------------------------------------------------------------------
// Kernel 3: streaming epilogue (write-bound, 537 MB).
// Block = (t, branch, 8-row i-tile); warp w handles j in [w*32, w*32+32).
// j OUTER, i inner: each b4 load is reused for 8 i-rows (loads 512MB -> 64MB),
// p[ii] = fma(a,s,h) precomputed in registers. Streaming stores (__stcs)
// keep the output from evicting B rows out of L2.
// ---------------------------------------------------------------------------
__global__ void __launch_bounds__(256) edge_kernel(float* __restrict__ out) {
    const int bid = blockIdx.x;          // 512 blocks
    const int itile = bid & 31;
    const int br = (bid >> 5) & 1;
    const int t = bid >> 6;
    const int i0 = itile * 8;
    const int tid = threadIdx.x;
    const int w = tid >> 5, l = tid & 31;
    const int f0 = l * 4;

    const float4 s4 = *(const float4*)&g_sh[br * 256 + f0];
    const float4 h4 = *(const float4*)&g_sh[br * 256 + 128 + f0];
    const int baseA = br * 256 + f0;
    const int baseB = baseA + 128;

    float4 p[8];
    #pragma unroll
    for (int ii = 0; ii < 8; ii++) {
        const float4 a4 = *(const float4*)&g_Y[(t * 256 + i0 + ii) * O_DIM + baseA];
        p[ii].x = fmaf(a4.x, s4.x, h4.x);
        p[ii].y = fmaf(a4.y, s4.y, h4.y);
        p[ii].z = fmaf(a4.z, s4.z, h4.z);
        p[ii].w = fmaf(a4.w, s4.w, h4.w);
    }

    // out index: (((t*2+br)*256 + i) * 256 + j) * 128 + f
    const size_t outbase = (size_t)((t * 2 + br) * 256 + i0) * (256 * 128);

    #pragma unroll 2
    for (int jj = 0; jj < 32; jj++) {
        const int j = w * 32 + jj;
        const float4 b4 = *(const float4*)&g_Y[(t * 256 + j) * O_DIM + baseB];
        float* orow = out + outbase + (size_t)j * 128 + f0;
        #pragma unroll
        for (int ii = 0; ii < 8; ii++) {
            float vx = fmaxf(fmaf(b4.x, s4.x, p[ii].x), 0.0f);
            float vy = fmaxf(fmaf(b4.y, s4.y, p[ii].y), 0.0f);
            float vz = fmaxf(fmaf(b4.z, s4.z, p[ii].z), 0.0f);
            float vw = fmaxf(fmaf(b4.w, s4.w, p[ii].w), 0.0f);
            if (j == i0 + ii) { vx = 0.f; vy = 0.f; vz = 0.f; vw = 0.f; }
            float sm = (vx + vy) + (vz + vw);
            #pragma unroll
            for (int off = 16; off; off >>= 1)
                sm += __shfl_xor_sync(0xffffffffu, sm, off);
            const float inv = __fdividef(1.0f, fmaxf(sm, 1e-12f));
            float4 o4 = make_float4(vx * inv, vy * inv, vz * inv, vw * inv);
            __stcs((float4*)(orow + (size_t)ii * (256 * 128)), o4);
        }
    }
}

// ---------------------------------------------------------------------------
extern "C" void kernel_launch(void* const* d_in, const int* in_sizes, int n_in,
                              void* d_out, int out_size) {
    const float* x  = (const float*)d_in[0];   // node_feats [8,256,128]
    const float* w1 = (const float*)d_in[1];   // [128,256]
    const float* g1 = (const float*)d_in[2];
    const float* b1 = (const float*)d_in[3];
    const float* w2 = (const float*)d_in[4];
    const float* g2 = (const float*)d_in[5];
    const float* b2 = (const float*)d_in[6];
    float* out = (float*)d_out;                // [8,2,256,256,128] fp32

    dim3 ggrid(O_DIM / 64, M_DIM / 32);        // (8, 64)
    gemm_kernel<<<ggrid, 256>>>(x, w1, w2);
    stats_kernel<<<256, 256>>>(g1, b1, g2, b2);
    edge_kernel<<<512, 256>>>(out);
}

// round 6
// speedup vs baseline: 1.4566x; 1.0877x over previous
#include <cuda_runtime.h>

// EdgeUpdateNetwork: T=8, N=256, F=128
//
// Factorization: y[t,i,j,f] = A[t,i,f] + B[t,j,f] where
//   A = x @ w[:, :F]^T,  B = x @ w[:, F:]^T
// BN stats in closed form from A/B reductions; then fused
// affine+relu+diag-zero+L1-normalize streaming kernel writes 537MB.

#define T_DIM 8
#define N_DIM 256
#define F_DIM 128
#define M_DIM (T_DIM * N_DIM)   // 2048 rows
#define O_DIM 512               // A1 | B1 | A2 | B2

// Scratch (device globals — no allocation allowed)
__device__ float g_Y[M_DIM * O_DIM];   // 4 MB: Y[m][o]
__device__ float g_sh[4 * F_DIM];      // [br*256 + f] = scale, [br*256+128+f] = shift

// ---------------------------------------------------------------------------
// Kernel 1: X[2048,128] @ W^T[128,512] -> Y[2048,512]
// 128x64 tile per block, grid (8,16)=128 blocks (one wave), 256 threads,
// 8x4 micro-tile (1.5 B smem per lane-FMA -> below FFMA floor),
// register-prefetch pipeline over 8 K-chunks of 16.
// ---------------------------------------------------------------------------
__global__ void __launch_bounds__(256) gemm_kernel(const float* __restrict__ X,
                                                   const float* __restrict__ w1,
                                                   const float* __restrict__ w2) {
    __shared__ float Xs[16][132];   // [kk][m]  row stride 528B (16B aligned)
    __shared__ float Ws[16][68];    // [kk][o]  row stride 272B (16B aligned)

    const int m0 = blockIdx.y * 128;
    const int o0 = blockIdx.x * 64;
    const int tid = threadIdx.x;
    const int tx = tid & 15;        // o-group: cols tx*4 .. tx*4+3
    const int ty = tid >> 4;        // m-group: rows ty*8 .. ty*8+7
    const float* wbase = (o0 < 256) ? w1 : w2;   // o0 multiple of 64, never straddles

    // X loads: 512 float4 per chunk, 2 per thread.  u = tid*2+r
    const int ux0 = tid * 2, ux1 = tid * 2 + 1;
    const int xr0 = ux0 >> 2, xq0 = ux0 & 3;
    const int xr1 = ux1 >> 2, xq1 = ux1 & 3;
    // W loads: 256 float4 per chunk, 1 per thread.
    const int wo = tid >> 2, wq = tid & 3;
    const int wf = (o0 + wo) & 127, wh = ((o0 + wo) >> 7) & 1;
    const float* wptr = wbase + wf * 256 + wh * 128 + wq * 4;

    float acc[8][4] = {};
    float4 px0, px1, pw;

    // prefetch chunk 0
    px0 = *(const float4*)&X[(m0 + xr0) * 128 + 0 + xq0 * 4];
    px1 = *(const float4*)&X[(m0 + xr1) * 128 + 0 + xq1 * 4];
    pw  = *(const float4*)&wptr[0];

    #pragma unroll
    for (int c = 0; c < 8; c++) {
        // regs -> smem (transpose to [kk][dim])
        Xs[xq0 * 4 + 0][xr0] = px0.x;  Xs[xq0 * 4 + 1][xr0] = px0.y;
        Xs[xq0 * 4 + 2][xr0] = px0.z;  Xs[xq0 * 4 + 3][xr0] = px0.w;
        Xs[xq1 * 4 + 0][xr1] = px1.x;  Xs[xq1 * 4 + 1][xr1] = px1.y;
        Xs[xq1 * 4 + 2][xr1] = px1.z;  Xs[xq1 * 4 + 3][xr1] = px1.w;
        Ws[wq * 4 + 0][wo] = pw.x;     Ws[wq * 4 + 1][wo] = pw.y;
        Ws[wq * 4 + 2][wo] = pw.z;     Ws[wq * 4 + 3][wo] = pw.w;
        __syncthreads();

        if (c < 7) {
            const int kc = (c + 1) * 16;
            px0 = *(const float4*)&X[(m0 + xr0) * 128 + kc + xq0 * 4];
            px1 = *(const float4*)&X[(m0 + xr1) * 128 + kc + xq1 * 4];
            pw  = *(const float4*)&wptr[kc];
        }

        #pragma unroll
        for (int kk = 0; kk < 16; kk++) {
            const float4 xa = *(const float4*)&Xs[kk][ty * 8];
            const float4 xb = *(const float4*)&Xs[kk][ty * 8 + 4];
            const float4 wr = *(const float4*)&Ws[kk][tx * 4];
            const float xv[8] = {xa.x, xa.y, xa.z, xa.w, xb.x, xb.y, xb.z, xb.w};
            const float wv[4] = {wr.x, wr.y, wr.z, wr.w};
            #pragma unroll
            for (int a = 0; a < 8; a++)
                #pragma unroll
                for (int b = 0; b < 4; b++)
                    acc[a][b] = fmaf(xv[a], wv[b], acc[a][b]);
        }
        __syncthreads();
    }

    #pragma unroll
    for (int a = 0; a < 8; a++) {
        float4 v = make_float4(acc[a][0], acc[a][1], acc[a][2], acc[a][3]);
        *(float4*)&g_Y[(m0 + ty * 8 + a) * O_DIM + o0 + tx * 4] = v;
    }
}

// ---------------------------------------------------------------------------
// Kernel 2: closed-form BN stats per (branch, f).
//   mean = (sumA + sumB) / (T*N)
//   E[y^2] = (N*(sumA2 + sumB2) + 2*sum_t SA_t*SB_t) / (T*N*N)
//   fold: s = g * rsqrt(var+eps), h = b - mean*s
// ---------------------------------------------------------------------------
__global__ void stats_kernel(const float* __restrict__ gamma1,
                             const float* __restrict__ beta1,
                             const float* __restrict__ gamma2,
                             const float* __restrict__ beta2) {
    const int bf = blockIdx.x;
    const int br = bf >> 7, f = bf & 127;
    const int colA = br * 256 + f;
    const int colB = colA + 128;
    const int tid = threadIdx.x;

    float sa = 0.f, sa2 = 0.f, sb = 0.f, sb2 = 0.f;
    #pragma unroll
    for (int k = 0; k < 8; k++) {
        int m = tid * 8 + k;
        float a = g_Y[m * O_DIM + colA];
        float b = g_Y[m * O_DIM + colB];
        sa += a;  sa2 = fmaf(a, a, sa2);
        sb += b;  sb2 = fmaf(b, b, sb2);
    }
    #pragma unroll
    for (int off = 16; off; off >>= 1) {
        sa  += __shfl_xor_sync(0xffffffffu, sa,  off);
        sa2 += __shfl_xor_sync(0xffffffffu, sa2, off);
        sb  += __shfl_xor_sync(0xffffffffu, sb,  off);
        sb2 += __shfl_xor_sync(0xffffffffu, sb2, off);
    }
    __shared__ float SA[8], SB[8], SA2[8], SB2[8];
    int w = tid >> 5;
    if ((tid & 31) == 0) { SA[w] = sa; SB[w] = sb; SA2[w] = sa2; SB2[w] = sb2; }
    __syncthreads();
    if (tid == 0) {
        float sumA = 0.f, sumB = 0.f, sumA2 = 0.f, sumB2 = 0.f, cross = 0.f;
        #pragma unroll
        for (int t = 0; t < 8; t++) {
            sumA  += SA[t];  sumB  += SB[t];
            sumA2 += SA2[t]; sumB2 += SB2[t];
            cross = fmaf(SA[t], SB[t], cross);
        }
        float mean = (sumA + sumB) * (1.0f / 2048.0f);
        float ey2  = (256.0f * (sumA2 + sumB2) + 2.0f * cross) * (1.0f / 524288.0f);
        float var  = ey2 - mean * mean;
        float g  = br ? gamma2[f] : gamma1[f];
        float bb = br ? beta2[f]  : beta1[f];
        float s  = g * rsqrtf(var + 1e-5f);
        g_sh[br * 256 + f]       = s;
        g_sh[br * 256 + 128 + f] = bb - mean * s;
    }
}

// ---------------------------------------------------------------------------
// Kernel 3: streaming epilogue (write-bound, 537 MB).
// Block = (t, branch, 8-row i-tile); warp w handles j in [w*32, w*32+32).
// j OUTER, i inner: each b4 load is reused for 8 i-rows,
// p[ii] = fma(a,s,h) precomputed in registers. Streaming stores (__stcs).
// ---------------------------------------------------------------------------
__global__ void __launch_bounds__(256) edge_kernel(float* __restrict__ out) {
    const int bid = blockIdx.x;          // 512 blocks
    const int itile = bid & 31;
    const int br = (bid >> 5) & 1;
    const int t = bid >> 6;
    const int i0 = itile * 8;
    const int tid = threadIdx.x;
    const int w = tid >> 5, l = tid & 31;
    const int f0 = l * 4;

    const float4 s4 = *(const float4*)&g_sh[br * 256 + f0];
    const float4 h4 = *(const float4*)&g_sh[br * 256 + 128 + f0];
    const int baseA = br * 256 + f0;
    const int baseB = baseA + 128;

    float4 p[8];
    #pragma unroll
    for (int ii = 0; ii < 8; ii++) {
        const float4 a4 = *(const float4*)&g_Y[(t * 256 + i0 + ii) * O_DIM + baseA];
        p[ii].x = fmaf(a4.x, s4.x, h4.x);
        p[ii].y = fmaf(a4.y, s4.y, h4.y);
        p[ii].z = fmaf(a4.z, s4.z, h4.z);
        p[ii].w = fmaf(a4.w, s4.w, h4.w);
    }

    // out index: (((t*2+br)*256 + i) * 256 + j) * 128 + f
    const size_t outbase = (size_t)((t * 2 + br) * 256 + i0) * (256 * 128);

    #pragma unroll 2
    for (int jj = 0; jj < 32; jj++) {
        const int j = w * 32 + jj;
        const float4 b4 = *(const float4*)&g_Y[(t * 256 + j) * O_DIM + baseB];
        float* orow = out + outbase + (size_t)j * 128 + f0;
        #pragma unroll
        for (int ii = 0; ii < 8; ii++) {
            float vx = fmaxf(fmaf(b4.x, s4.x, p[ii].x), 0.0f);
            float vy = fmaxf(fmaf(b4.y, s4.y, p[ii].y), 0.0f);
            float vz = fmaxf(fmaf(b4.z, s4.z, p[ii].z), 0.0f);
            float vw = fmaxf(fmaf(b4.w, s4.w, p[ii].w), 0.0f);
            if (j == i0 + ii) { vx = 0.f; vy = 0.f; vz = 0.f; vw = 0.f; }
            float sm = (vx + vy) + (vz + vw);
            #pragma unroll
            for (int off = 16; off; off >>= 1)
                sm += __shfl_xor_sync(0xffffffffu, sm, off);
            const float inv = __fdividef(1.0f, fmaxf(sm, 1e-12f));
            float4 o4 = make_float4(vx * inv, vy * inv, vz * inv, vw * inv);
            __stcs((float4*)(orow + (size_t)ii * (256 * 128)), o4);
        }
    }
}

// ---------------------------------------------------------------------------
extern "C" void kernel_launch(void* const* d_in, const int* in_sizes, int n_in,
                              void* d_out, int out_size) {
    const float* x  = (const float*)d_in[0];   // node_feats [8,256,128]
    const float* w1 = (const float*)d_in[1];   // [128,256]
    const float* g1 = (const float*)d_in[2];
    const float* b1 = (const float*)d_in[3];
    const float* w2 = (const float*)d_in[4];
    const float* g2 = (const float*)d_in[5];
    const float* b2 = (const float*)d_in[6];
    float* out = (float*)d_out;                // [8,2,256,256,128] fp32

    dim3 ggrid(O_DIM / 64, M_DIM / 128);       // (8, 16) = 128 blocks
    gemm_kernel<<<ggrid, 256>>>(x, w1, w2);
    stats_kernel<<<256, 256>>>(g1, b1, g2, b2);
    edge_kernel<<<512, 256>>>(out);
}